// round 5
// baseline (speedup 1.0000x reference)
#include <cuda_runtime.h>
#include <math.h>

// mParametricLIF: x [N=128, T=64, D=4096] f32 -> spikes [N,T,D] f32.
// Per-(n,d) recurrence over t (elementwise in n,d; sequential in t):
//   m = lam*m + k*(x - v);  v += m;  s = (v >= th);  v = s ? 0 : v;  out = s
// k = sigmoid(tau_param[0]), lam = lamb[0], th = th[0].
//
// R5 = R4 resubmit (R4 bench was an infra failure, theory untested):
//  - float2 lanes: 262144 threads (2048 blocks x 128) -> ~55 warps/SM
//  - __launch_bounds__(128,16) caps regs at 32 so all 2048 blocks are
//    co-resident in ONE wave (148*16 = 2368 block slots)
//  - TUNROLL=4 to fit the reg budget; chip MLP unchanged (2x threads)
//  - __ldcs/__stcs kept (R2 evidence: prevents load folding; streaming out)

#ifndef TUNROLL
#define TUNROLL 4
#endif

__global__ __launch_bounds__(128, 16) void mplif_kernel(
    const float2* __restrict__ x2,
    const float* __restrict__ tau_param,
    const float* __restrict__ lamb,
    const float* __restrict__ thr,
    float2* __restrict__ out2,
    int T, int DC /* D/2 */, int lanes /* N*DC */)
{
    int tid = blockIdx.x * blockDim.x + threadIdx.x;
    if (tid >= lanes) return;

    int n = tid / DC;
    int c = tid - n * DC;
    long base = (long)n * T * DC + c;

    const float k   = 1.0f / (1.0f + expf(-tau_param[0]));
    const float lam = lamb[0];
    const float th  = thr[0];

    float2 v = make_float2(0.f, 0.f);
    float2 m = make_float2(0.f, 0.f);

    float2 buf[TUNROLL];

    for (int t0 = 0; t0 < T; t0 += TUNROLL) {
        // Batch independent streaming loads (MLP = TUNROLL LDG.64).
        #pragma unroll
        for (int j = 0; j < TUNROLL; j++) {
            buf[j] = __ldcs(&x2[base + (long)(t0 + j) * DC]);
        }
        // Serial recurrence on registers.
        #pragma unroll
        for (int j = 0; j < TUNROLL; j++) {
            float2 xv = buf[j];
            float2 s;

            m.x = lam * m.x + k * (xv.x - v.x); v.x += m.x;
            m.y = lam * m.y + k * (xv.y - v.y); v.y += m.y;

            s.x = (v.x >= th) ? 1.0f : 0.0f;
            s.y = (v.y >= th) ? 1.0f : 0.0f;

            v.x = (s.x != 0.0f) ? 0.0f : v.x;
            v.y = (s.y != 0.0f) ? 0.0f : v.y;

            __stcs(&out2[base + (long)(t0 + j) * DC], s);
        }
    }
}

extern "C" void kernel_launch(void* const* d_in, const int* in_sizes, int n_in,
                              void* d_out, int out_size)
{
    const float* x         = (const float*)d_in[0];
    const float* tau_param = (const float*)d_in[1];
    const float* lamb      = (const float*)d_in[2];
    const float* th        = (const float*)d_in[3];
    float* out             = (float*)d_out;

    const int N = 128, T = 64, D = 4096;
    const int DC = D / 2;
    const int lanes = N * DC;

    dim3 block(128);
    dim3 grid((lanes + block.x - 1) / block.x);  // 2048 blocks
    mplif_kernel<<<grid, block>>>((const float2*)x, tau_param, lamb, th,
                                  (float2*)out, T, DC, lanes);
}

// round 8
// speedup vs baseline: 1.1482x; 1.1482x over previous
#include <cuda_runtime.h>
#include <math.h>

// mParametricLIF: x [N=128, T=64, D=4096] f32 -> spikes [N,T,D] f32.
// Per-(n,d) recurrence over t (elementwise in n,d; sequential in t):
//   m = lam*m + k*(x - v);  v += m;  s = (v >= th);  v = s ? 0 : v;  out = s
// k = sigmoid(tau_param[0]), lam = lamb[0], th = th[0].
//
// R8 = R6/R7 pipeline theory, third submission (R6, R7 both died to
// transient broker "container failed twice" errors; same class as R4 which
// passed on identical resubmit). Functional content unchanged; index math
// hoisted into rolling pointers (fewer 64-bit IMADs per step).
//  - rolling software pipeline, prefetch distance 8: each step consumes
//    buf[j], issues the load for t+8 into buf[j], computes, stores.
//    ~8 LDG.128 always in flight per thread; LDG/STG interleaved.
//  - float4 lanes, block=128 grid=1024, __ldcs/__stcs (all R2-proven).

#define TU 8

__device__ __forceinline__ void lif_step(float4 xv, float4& v, float4& m,
                                         float k, float lam, float th,
                                         float4& s)
{
    m.x = lam * m.x + k * (xv.x - v.x); v.x += m.x;
    m.y = lam * m.y + k * (xv.y - v.y); v.y += m.y;
    m.z = lam * m.z + k * (xv.z - v.z); v.z += m.z;
    m.w = lam * m.w + k * (xv.w - v.w); v.w += m.w;

    s.x = (v.x >= th) ? 1.0f : 0.0f;
    s.y = (v.y >= th) ? 1.0f : 0.0f;
    s.z = (v.z >= th) ? 1.0f : 0.0f;
    s.w = (v.w >= th) ? 1.0f : 0.0f;

    v.x = (s.x != 0.0f) ? 0.0f : v.x;
    v.y = (s.y != 0.0f) ? 0.0f : v.y;
    v.z = (s.z != 0.0f) ? 0.0f : v.z;
    v.w = (s.w != 0.0f) ? 0.0f : v.w;
}

__global__ __launch_bounds__(128) void mplif_kernel(
    const float4* __restrict__ x4,
    const float* __restrict__ tau_param,
    const float* __restrict__ lamb,
    const float* __restrict__ thr,
    float4* __restrict__ out4,
    int T, int DC /* D/4 */, int lanes /* N*DC */)
{
    int tid = blockIdx.x * blockDim.x + threadIdx.x;
    if (tid >= lanes) return;

    int n = tid / DC;
    int c = tid - n * DC;
    long base = (long)n * T * DC + c;

    const float k   = 1.0f / (1.0f + expf(-tau_param[0]));
    const float lam = lamb[0];
    const float th  = thr[0];

    float4 v = make_float4(0.f, 0.f, 0.f, 0.f);
    float4 m = make_float4(0.f, 0.f, 0.f, 0.f);

    float4 buf[TU];

    const float4* __restrict__ px = x4 + base;      // prefetch cursor
    float4*       __restrict__ po = out4 + base;    // store cursor

    // Prologue: fill pipeline with first TU loads.
    #pragma unroll
    for (int j = 0; j < TU; j++) {
        buf[j] = __ldcs(px);
        px += DC;
    }

    // Steady state: consume buf[j] (timestep t0+j), refill with t0+TU+j.
    for (int t0 = 0; t0 < T - TU; t0 += TU) {
        #pragma unroll
        for (int j = 0; j < TU; j++) {
            float4 xv = buf[j];
            buf[j] = __ldcs(px);
            px += DC;
            float4 s;
            lif_step(xv, v, m, k, lam, th, s);
            __stcs(po, s);
            po += DC;
        }
    }

    // Epilogue: last TU timesteps, no prefetch.
    #pragma unroll
    for (int j = 0; j < TU; j++) {
        float4 s;
        lif_step(buf[j], v, m, k, lam, th, s);
        __stcs(po, s);
        po += DC;
    }
}

extern "C" void kernel_launch(void* const* d_in, const int* in_sizes, int n_in,
                              void* d_out, int out_size)
{
    const float* x         = (const float*)d_in[0];
    const float* tau_param = (const float*)d_in[1];
    const float* lamb      = (const float*)d_in[2];
    const float* th        = (const float*)d_in[3];
    float* out             = (float*)d_out;

    const int N = 128, T = 64, D = 4096;
    const int DC = D / 4;
    const int lanes = N * DC;

    dim3 block(128);
    dim3 grid((lanes + block.x - 1) / block.x);  // 1024 blocks
    mplif_kernel<<<grid, block>>>((const float4*)x, tau_param, lamb, th,
                                  (float4*)out, T, DC, lanes);
}